// round 12
// baseline (speedup 1.0000x reference)
#include <cuda_runtime.h>
#include <cuda_fp16.h>
#include <cstdint>

// Problem constants
#define BB 64
#define SS 2048
#define HH 512
#define KK 512

// Scratch (static __device__ — no allocation)
__device__ float  g_c[BB * KK];            // e_fin + bias
__device__ float  g_scores[BB * SS];       // scores, then softmax weights
__device__ float  g_part[BB * 16 * HH];    // context partial sums
__device__ __half g_ench[(size_t)BB * SS * HH];   // enc in fp16 (written by scores)
__device__ __half g_wh[KK * HH];                  // w_enc in fp16

// ---------------------------------------------------------------------------
// helpers
// ---------------------------------------------------------------------------
__device__ __forceinline__ float tanha(float x) {
    float y;
    asm("tanh.approx.f32 %0, %1;" : "=f"(y) : "f"(x));
    return y;
}
__device__ __forceinline__ void cp16(uint32_t dst, const void* src) {
    asm volatile("cp.async.cg.shared.global [%0], [%1], 16;" :: "r"(dst), "l"(src));
}
__device__ __forceinline__ void cp_commit() {
    asm volatile("cp.async.commit_group;");
}
__device__ __forceinline__ void ldsm4(uint32_t (&r)[4], uint32_t addr) {
    asm volatile("ldmatrix.sync.aligned.m8n8.x4.shared.b16 {%0,%1,%2,%3}, [%4];"
                 : "=r"(r[0]), "=r"(r[1]), "=r"(r[2]), "=r"(r[3]) : "r"(addr));
}
// fp16-accumulator mma: D (fp16x2 pair) = A*B + C, C passed separately so the
// first K-step can use C=0 (no accumulator zeroing).
__device__ __forceinline__ void mma_h(uint32_t& d0, uint32_t& d1,
                                      const uint32_t (&a)[4],
                                      uint32_t b0, uint32_t b1,
                                      uint32_t c0, uint32_t c1) {
    asm volatile(
        "mma.sync.aligned.m16n8k16.row.col.f16.f16.f16.f16 "
        "{%0,%1},{%2,%3,%4,%5},{%6,%7},{%8,%9};"
        : "=r"(d0), "=r"(d1)
        : "r"(a[0]), "r"(a[1]), "r"(a[2]), "r"(a[3]), "r"(b0), "r"(b1),
          "r"(c0), "r"(c1));
}
__device__ __forceinline__ uint32_t h2u(__half2 h) {
    return *reinterpret_cast<uint32_t*>(&h);
}
__device__ __forceinline__ float2 u2f2(uint32_t u) {
    return __half22float2(*reinterpret_cast<const __half2*>(&u));
}

// ---------------------------------------------------------------------------
// conv_w: w_enc fp32 -> fp16
// ---------------------------------------------------------------------------
__global__ void conv_w_kernel(const float* __restrict__ attn_w) {
    int k = blockIdx.x, t = threadIdx.x;
    float2 v = *(const float2*)(attn_w + (size_t)k * (2 * HH) + 2 * t);
    ((__half2*)g_wh)[k * (HH / 2) + t] = __floats2half2_rn(v.x, v.y);
}

// ---------------------------------------------------------------------------
// Kernel A: c[b,k] = dot(fin[b,:], attn_w[k, 512:1024]) + attn_b[k]  (fp32)
// ---------------------------------------------------------------------------
__global__ void cvec_kernel(const float* __restrict__ fin,
                            const float* __restrict__ attn_w,
                            const float* __restrict__ attn_b) {
    __shared__ float fsm[HH];
    int b = blockIdx.x;
    int t = threadIdx.x;
    fsm[t] = fin[b * HH + t];
    fsm[t + 256] = fin[b * HH + t + 256];
    __syncthreads();

    int warp = t >> 5, lane = t & 31;
    for (int k = warp; k < KK; k += 8) {
        const float* wp = attn_w + (size_t)k * (2 * HH) + HH;
        float s = 0.f;
        #pragma unroll 4
        for (int h = lane; h < HH; h += 32) s += fsm[h] * wp[h];
        #pragma unroll
        for (int o = 16; o > 0; o >>= 1) s += __shfl_xor_sync(0xffffffffu, s, o);
        if (lane == 0) g_c[b * KK + k] = s + attn_b[k];
    }
}

// ---------------------------------------------------------------------------
// Kernel B: fused scores = sum_k v[k]*tanh(enc @ w_enc^T + c).
// fp16 mma with FP16 ACCUMULATORS (full-rate tensor pipe), flushed to fp32
// master accumulators once per 64-h chunk (3 fp16 roundings per chunk).
// grid(16, 64): 128-s tile (x), batch (y). 256 thr = 8 warps (2 warp_m x 4
// warp_n), warp tile 64m x 64k. Block n-tile 256, 2 kc passes, 16 chunks.
// A (fp32 enc) converted/STS'd slice-by-slice under the mainloop (and STG'd
// fp16 to g_ench). B double-buffered cp.async.
//
// SMEM (bytes): cs[512]f32 @0, vs[512]f32 @2048, ssum[4][128]f32 @4096,
//               A @8192 (128 rows x 1024B, XOR (row&7)<<4),
//               B @139264 (2 bufs x 256 rows x 128B, XOR (row&7)<<4)
// ---------------------------------------------------------------------------
#define SM_CS   0
#define SM_VS   2048
#define SM_SSUM 4096
#define SM_A    8192
#define SM_B    139264
#define BBUF    32768
#define SMEM_BYTES 204800

extern __shared__ uint32_t sdyn[];

__global__ __launch_bounds__(256, 1) void scores_fp16(
    const float* __restrict__ enc, const float* __restrict__ vw) {
    const int b = blockIdx.y;
    const int s0 = blockIdx.x * 128;
    const int tid = threadIdx.x;
    const int warp = tid >> 5, lane = tid & 31;
    const int g = lane >> 2, tg = lane & 3;
    const int warp_m = warp >> 2;      // 0..1  -> 64-row slices
    const int warp_n = warp & 3;       // 0..3  -> 64-k slices
    const uint32_t sbase = (uint32_t)__cvta_generic_to_shared(sdyn);

    float* cs = (float*)((char*)sdyn + SM_CS);
    float* vs = (float*)((char*)sdyn + SM_VS);
    float* ssum = (float*)((char*)sdyn + SM_SSUM);

    cs[tid] = g_c[b * KK + tid];
    cs[tid + 256] = g_c[b * KK + tid + 256];
    vs[tid] = vw[tid];
    vs[tid + 256] = vw[tid + 256];
    ssum[tid] = 0.f;
    ssum[tid + 256] = 0.f;

    // ---- B chunk loader: kc=(c>>3)*256, h0=(c&7)*64 halves; 128B rows ----
    auto loadB = [&](int c) {
        const uint32_t bb = sbase + SM_B + (c & 1) * BBUF;
        const int kc = (c >> 3) << 8;
        const int h0 = (c & 7) << 6;
        #pragma unroll
        for (int i = 0; i < 8; i++) {
            int idx = tid + i * 256;            // 0..2047
            int row = idx >> 3, u = idx & 7;
            uint32_t dst = bb + row * 128 + ((u * 16) ^ ((row & 7) << 4));
            cp16(dst, g_wh + (size_t)(kc + row) * HH + h0 + u * 8);
        }
        cp_commit();
    };
    loadB(0);

    // ---- A slice pipeline: slice j = h halves [j*64, j*64+64) ----
    // 256 thr: thread owns row = tid>>1, 4 16B-units u = (tid&1)*4 .. +3.
    const float* asrc = enc + ((size_t)b * SS + s0) * HH;
    __half* edst = g_ench + ((size_t)b * SS + s0) * HH;
    const int ar = tid >> 1, aub = (tid & 1) * 4;
    float4 av[8];

    auto ldgA = [&](int j) {
        const float* p = asrc + (size_t)ar * HH + j * 64 + aub * 8;
        #pragma unroll
        for (int k = 0; k < 4; k++) {
            av[2 * k]     = ((const float4*)p)[2 * k];
            av[2 * k + 1] = ((const float4*)p)[2 * k + 1];
        }
    };
    auto stsA = [&](int j) {
        #pragma unroll
        for (int k = 0; k < 4; k++) {
            uint32_t w0 = h2u(__floats2half2_rn(av[2*k].x, av[2*k].y));
            uint32_t w1 = h2u(__floats2half2_rn(av[2*k].z, av[2*k].w));
            uint32_t w2 = h2u(__floats2half2_rn(av[2*k+1].x, av[2*k+1].y));
            uint32_t w3 = h2u(__floats2half2_rn(av[2*k+1].z, av[2*k+1].w));
            uint32_t col = (uint32_t)(j * 128 + (aub + k) * 16);
            uint32_t d0 = sbase + SM_A + ar * 1024 + (col ^ ((ar & 7) << 4));
            asm volatile("st.shared.v4.b32 [%0], {%1,%2,%3,%4};"
                         :: "r"(d0), "r"(w0), "r"(w1), "r"(w2), "r"(w3));
            *(uint4*)(edst + (size_t)ar * HH + j * 64 + (aub + k) * 8) =
                make_uint4(w0, w1, w2, w3);
        }
    };
    ldgA(0);

    // ---- lane-constant ldmatrix addressing ----
    const int arow = warp_m * 64 + (lane & 7) + ((lane >> 3) & 1) * 8;   // +mi*16
    const int brow = warp_n * 64 + (lane & 7) + ((lane >> 3) & 1) * 8;   // +ng*32+nip*16
    const int lcol16 = ((lane >> 4) & 1) * 16;    // +16B for k+8 halves
    const uint32_t a_lane = sbase + SM_A + arow * 1024;
    const uint32_t xor_a = (arow & 7) << 4;
    const uint32_t xor_b = (brow & 7) << 4;

    float acc[4][8][4];   // fp32 master accumulators
    #pragma unroll
    for (int mi = 0; mi < 4; mi++)
        #pragma unroll
        for (int ni = 0; ni < 8; ni++)
            #pragma unroll
            for (int q = 0; q < 4; q++) acc[mi][ni][q] = 0.f;

    #pragma unroll 1
    for (int c = 0; c < 16; c++) {
        if (c < 8) stsA(c);         // slice c -> smem (visible after barrier)
        if (c < 15) {
            loadB(c + 1);
            asm volatile("cp.async.wait_group 1;");
        } else {
            asm volatile("cp.async.wait_group 0;");
        }
        __syncthreads();
        if (c < 7) ldgA(c + 1);     // hidden under this chunk's mma

        const uint32_t bb = sbase + SM_B + (c & 1) * BBUF + brow * 128;
        const int hbase = (c & 7) * 128;   // byte offset of chunk within A row

        // two n32 sub-passes so fp16 chunk-accumulators stay at 32 regs
        #pragma unroll
        for (int ng = 0; ng < 2; ng++) {
            uint32_t hacc[4][4][2];
            #pragma unroll
            for (int kk = 0; kk < 4; kk++) {
                const uint32_t hoff = (uint32_t)(hbase + kk * 32 + lcol16);
                uint32_t a[4][4];
                #pragma unroll
                for (int mi = 0; mi < 4; mi++)
                    ldsm4(a[mi], a_lane + mi * 16384 + (hoff ^ xor_a));
                #pragma unroll
                for (int nip = 0; nip < 2; nip++) {
                    uint32_t r[4];
                    ldsm4(r, bb + ng * 4096 + nip * 2048 +
                              (((uint32_t)(kk * 32 + lcol16)) ^ xor_b));
                    #pragma unroll
                    for (int mi = 0; mi < 4; mi++) {
                        if (kk == 0) {
                            mma_h(hacc[mi][2*nip][0], hacc[mi][2*nip][1],
                                  a[mi], r[0], r[2], 0u, 0u);
                            mma_h(hacc[mi][2*nip+1][0], hacc[mi][2*nip+1][1],
                                  a[mi], r[1], r[3], 0u, 0u);
                        } else {
                            mma_h(hacc[mi][2*nip][0], hacc[mi][2*nip][1],
                                  a[mi], r[0], r[2],
                                  hacc[mi][2*nip][0], hacc[mi][2*nip][1]);
                            mma_h(hacc[mi][2*nip+1][0], hacc[mi][2*nip+1][1],
                                  a[mi], r[1], r[3],
                                  hacc[mi][2*nip+1][0], hacc[mi][2*nip+1][1]);
                        }
                    }
                }
            }
            // flush fp16 chunk acc -> fp32 master
            #pragma unroll
            for (int mi = 0; mi < 4; mi++)
                #pragma unroll
                for (int j = 0; j < 4; j++) {
                    int ni = ng * 4 + j;
                    float2 lo = u2f2(hacc[mi][j][0]);   // row g,  cols tg*2,+1
                    float2 hi = u2f2(hacc[mi][j][1]);   // row g+8
                    acc[mi][ni][0] += lo.x; acc[mi][ni][1] += lo.y;
                    acc[mi][ni][2] += hi.x; acc[mi][ni][3] += hi.y;
                }
        }

        if ((c & 7) == 7) {
            // epilogue for this kc: tanh(acc + c)*v, reduce 64 k per warp
            const int kc = (c >> 3) << 8;
            float rs[8];
            #pragma unroll
            for (int i = 0; i < 8; i++) rs[i] = 0.f;
            #pragma unroll
            for (int ni = 0; ni < 8; ni++) {
                int kg = kc + warp_n * 64 + ni * 8 + tg * 2;
                float c0 = cs[kg], c1 = cs[kg + 1];
                float v0 = vs[kg], v1 = vs[kg + 1];
                #pragma unroll
                for (int mi = 0; mi < 4; mi++) {
                    rs[mi * 2 + 0] += tanha(acc[mi][ni][0] + c0) * v0
                                    + tanha(acc[mi][ni][1] + c1) * v1;
                    rs[mi * 2 + 1] += tanha(acc[mi][ni][2] + c0) * v0
                                    + tanha(acc[mi][ni][3] + c1) * v1;
                    acc[mi][ni][0] = 0.f; acc[mi][ni][1] = 0.f;
                    acc[mi][ni][2] = 0.f; acc[mi][ni][3] = 0.f;
                }
            }
            #pragma unroll
            for (int i = 0; i < 8; i++) {
                rs[i] += __shfl_xor_sync(0xffffffffu, rs[i], 1);
                rs[i] += __shfl_xor_sync(0xffffffffu, rs[i], 2);
            }
            if (tg == 0) {
                #pragma unroll
                for (int mi = 0; mi < 4; mi++) {
                    int row = warp_m * 64 + mi * 16 + g;
                    ssum[warp_n * 128 + row]     += rs[mi * 2 + 0];
                    ssum[warp_n * 128 + row + 8] += rs[mi * 2 + 1];
                }
            }
        }
        __syncthreads();
    }

    if (tid < 128) {
        g_scores[b * SS + s0 + tid] =
            (ssum[tid] + ssum[128 + tid]) + (ssum[256 + tid] + ssum[384 + tid]);
    }
}

// ---------------------------------------------------------------------------
// Kernel C: softmax over s (2048) per batch; in-place on g_scores
// ---------------------------------------------------------------------------
__global__ void softmax_kernel() {
    __shared__ float red[256];
    int b = blockIdx.x, t = threadIdx.x;
    float v[8];
    float m = -1e30f;
    #pragma unroll
    for (int i = 0; i < 8; i++) {
        v[i] = g_scores[b * SS + i * 256 + t];
        m = fmaxf(m, v[i]);
    }
    red[t] = m;
    __syncthreads();
    for (int o = 128; o > 0; o >>= 1) {
        if (t < o) red[t] = fmaxf(red[t], red[t + o]);
        __syncthreads();
    }
    float mx = red[0];
    __syncthreads();
    float s = 0.f;
    #pragma unroll
    for (int i = 0; i < 8; i++) {
        v[i] = __expf(v[i] - mx);
        s += v[i];
    }
    red[t] = s;
    __syncthreads();
    for (int o = 128; o > 0; o >>= 1) {
        if (t < o) red[t] += red[t + o];
        __syncthreads();
    }
    float inv = 1.f / red[0];
    #pragma unroll
    for (int i = 0; i < 8; i++)
        g_scores[b * SS + i * 256 + t] = v[i] * inv;
}

// ---------------------------------------------------------------------------
// Kernel D: context partials over 128-s chunks, fp16 enc (from scores STG)
// grid(16, 64), block(128); thread t owns h = 4t..4t+3
// ---------------------------------------------------------------------------
__global__ void context_kernel() {
    __shared__ float ws[128];
    int b = blockIdx.y, sc = blockIdx.x;
    int t = threadIdx.x;
    ws[t] = g_scores[b * SS + sc * 128 + t];
    __syncthreads();
    const __half* ep = g_ench + ((size_t)b * SS + sc * 128) * HH + 4 * t;
    float ax = 0.f, ay = 0.f, az = 0.f, aw = 0.f;
    #pragma unroll 4
    for (int j = 0; j < 128; j++) {
        float w = ws[j];
        uint2 u = *(const uint2*)(ep + (size_t)j * HH);
        float2 f0 = __half22float2(*reinterpret_cast<const __half2*>(&u.x));
        float2 f1 = __half22float2(*reinterpret_cast<const __half2*>(&u.y));
        ax += w * f0.x; ay += w * f0.y; az += w * f1.x; aw += w * f1.y;
    }
    float4 r; r.x = ax; r.y = ay; r.z = az; r.w = aw;
    ((float4*)(g_part + ((size_t)(b * 16 + sc)) * HH))[t] = r;
}

// ---------------------------------------------------------------------------
// Kernel E: reduce 16 partials -> context
// ---------------------------------------------------------------------------
__global__ void reduce_ctx(float* __restrict__ out) {
    int b = blockIdx.x, h = threadIdx.x;
    float s = 0.f;
    #pragma unroll
    for (int i = 0; i < 16; i++) s += g_part[((size_t)(b * 16 + i)) * HH + h];
    out[b * HH + h] = s;
}

// ---------------------------------------------------------------------------
extern "C" void kernel_launch(void* const* d_in, const int* in_sizes, int n_in,
                              void* d_out, int out_size) {
    const float* enc    = (const float*)d_in[0];   // (64, 2048, 512)
    const float* fin    = (const float*)d_in[1];   // (64, 512)
    const float* attn_w = (const float*)d_in[2];   // (512, 1024)
    const float* attn_b = (const float*)d_in[3];   // (512,)
    const float* v_w    = (const float*)d_in[4];   // (1, 512)
    float* out = (float*)d_out;                    // (64, 512)

    cudaFuncSetAttribute(scores_fp16,
                         cudaFuncAttributeMaxDynamicSharedMemorySize, SMEM_BYTES);

    conv_w_kernel<<<KK, 256>>>(attn_w);
    cvec_kernel<<<BB, 256>>>(fin, attn_w, attn_b);
    scores_fp16<<<dim3(SS / 128, BB), 256, SMEM_BYTES>>>(enc, v_w);
    softmax_kernel<<<BB, 256>>>();
    context_kernel<<<dim3(16, BB), 128>>>();
    reduce_ctx<<<BB, 512>>>(out);
}

// round 15
// speedup vs baseline: 1.3768x; 1.3768x over previous
#include <cuda_runtime.h>
#include <cuda_fp16.h>
#include <cstdint>

// Problem constants
#define BB 64
#define SS 2048
#define HH 512
#define KK 512

// Scratch (static __device__ — no allocation)
__device__ float  g_c[BB * KK];            // e_fin + bias
__device__ float  g_scores[BB * SS];       // scores, then softmax weights
__device__ float  g_part[BB * 16 * HH];    // context partial sums
__device__ __half g_ench[(size_t)BB * SS * HH];   // enc in fp16 (written by scores)
__device__ __half g_wh[KK * HH];                  // w_enc in fp16

// ---------------------------------------------------------------------------
// helpers
// ---------------------------------------------------------------------------
__device__ __forceinline__ float tanha(float x) {
    float y;
    asm("tanh.approx.f32 %0, %1;" : "=f"(y) : "f"(x));
    return y;
}
__device__ __forceinline__ void cp16(uint32_t dst, const void* src) {
    asm volatile("cp.async.cg.shared.global [%0], [%1], 16;" :: "r"(dst), "l"(src));
}
__device__ __forceinline__ void cp_commit() {
    asm volatile("cp.async.commit_group;");
}
__device__ __forceinline__ void ldsm4(uint32_t (&r)[4], uint32_t addr) {
    asm volatile("ldmatrix.sync.aligned.m8n8.x4.shared.b16 {%0,%1,%2,%3}, [%4];"
                 : "=r"(r[0]), "=r"(r[1]), "=r"(r[2]), "=r"(r[3]) : "r"(addr));
}
__device__ __forceinline__ void mma_f16(float (&d)[4], const uint32_t (&a)[4],
                                        uint32_t b0, uint32_t b1) {
    asm volatile(
        "mma.sync.aligned.m16n8k16.row.col.f32.f16.f16.f32 "
        "{%0,%1,%2,%3},{%4,%5,%6,%7},{%8,%9},{%0,%1,%2,%3};"
        : "+f"(d[0]), "+f"(d[1]), "+f"(d[2]), "+f"(d[3])
        : "r"(a[0]), "r"(a[1]), "r"(a[2]), "r"(a[3]), "r"(b0), "r"(b1));
}
__device__ __forceinline__ uint32_t h2u(__half2 h) {
    return *reinterpret_cast<uint32_t*>(&h);
}

// ---------------------------------------------------------------------------
// conv_w: w_enc fp32 -> fp16
// ---------------------------------------------------------------------------
__global__ void conv_w_kernel(const float* __restrict__ attn_w) {
    int k = blockIdx.x, t = threadIdx.x;
    float2 v = *(const float2*)(attn_w + (size_t)k * (2 * HH) + 2 * t);
    ((__half2*)g_wh)[k * (HH / 2) + t] = __floats2half2_rn(v.x, v.y);
}

// ---------------------------------------------------------------------------
// Kernel A: c[b,k] = dot(fin[b,:], attn_w[k, 512:1024]) + attn_b[k]  (fp32)
// ---------------------------------------------------------------------------
__global__ void cvec_kernel(const float* __restrict__ fin,
                            const float* __restrict__ attn_w,
                            const float* __restrict__ attn_b) {
    __shared__ float fsm[HH];
    int b = blockIdx.x;
    int t = threadIdx.x;
    fsm[t] = fin[b * HH + t];
    fsm[t + 256] = fin[b * HH + t + 256];
    __syncthreads();

    int warp = t >> 5, lane = t & 31;
    for (int k = warp; k < KK; k += 8) {
        const float* wp = attn_w + (size_t)k * (2 * HH) + HH;
        float s = 0.f;
        #pragma unroll 4
        for (int h = lane; h < HH; h += 32) s += fsm[h] * wp[h];
        #pragma unroll
        for (int o = 16; o > 0; o >>= 1) s += __shfl_xor_sync(0xffffffffu, s, o);
        if (lane == 0) g_c[b * KK + k] = s + attn_b[k];
    }
}

// ---------------------------------------------------------------------------
// Kernel B: fused scores = sum_k v[k]*tanh(enc @ w_enc^T + c), fp16 mma,
// fp32 accumulators. TWO CTAs PER SM (70 KB smem, <=128 regs): independent
// barrier domains cover each other's sync/epilogue/LDG bubbles.
// grid(16, 64): 128-s tile (x), batch (y). 256 thr = 8 warps (2 warp_m x 4
// warp_n), warp tile 64m x 32k. Block k-tile 128 per pass, 4 kc passes,
// 8 h-chunks (64 halves = 128B) per pass = 32 chunks total.
// A (fp32 enc): LDG+cvt to fp16 regs (hv[16]) at END of chunk c for slice
// c+1; STS at top of chunk c+1; double-buffered; re-streamed each pass
// (re-reads hit L2). g_ench STG on pass 0 only. B double-buffered cp.async.
//
// SMEM (bytes): cs[512]f32 @0, vs[512]f32 @2048, ssum[4][128]f32 @4096,
//               A @6144  (2 bufs x 128 rows x 128B, XOR (row&7)<<4),
//               B @38912 (2 bufs x 128 rows x 128B, XOR (row&7)<<4)
// total 71680 -> 2 CTAs/SM
// ---------------------------------------------------------------------------
#define SM_CS   0
#define SM_VS   2048
#define SM_SSUM 4096
#define SM_A    6144
#define ABUF    16384
#define SM_B    38912
#define BBUF    16384
#define SMEM_BYTES 71680

extern __shared__ uint32_t sdyn[];

__global__ __launch_bounds__(256, 2) void scores_fp16(
    const float* __restrict__ enc, const float* __restrict__ vw) {
    const int b = blockIdx.y;
    const int s0 = blockIdx.x * 128;
    const int tid = threadIdx.x;
    const int warp = tid >> 5, lane = tid & 31;
    const int g = lane >> 2, tg = lane & 3;
    const int warp_m = warp >> 2;      // 0..1  -> 64-row slices
    const int warp_n = warp & 3;       // 0..3  -> 32-k slices of the 128k pass
    const uint32_t sbase = (uint32_t)__cvta_generic_to_shared(sdyn);

    float* cs = (float*)((char*)sdyn + SM_CS);
    float* vs = (float*)((char*)sdyn + SM_VS);
    float* ssum = (float*)((char*)sdyn + SM_SSUM);

    cs[tid] = g_c[b * KK + tid];
    cs[tid + 256] = g_c[b * KK + tid + 256];
    vs[tid] = vw[tid];
    vs[tid + 256] = vw[tid + 256];
    ssum[tid] = 0.f;
    ssum[tid + 256] = 0.f;

    // ---- B chunk loader: pass p=c>>3 -> k rows [p*128,+128); h0=(c&7)*64 ----
    auto loadB = [&](int c) {
        const uint32_t bb = sbase + SM_B + (c & 1) * BBUF;
        const int kc = (c >> 3) << 7;
        const int h0 = (c & 7) << 6;
        #pragma unroll
        for (int i = 0; i < 4; i++) {
            int idx = tid + i * 256;            // 0..1023
            int row = idx >> 3, u = idx & 7;
            uint32_t dst = bb + row * 128 + ((u * 16) ^ ((row & 7) << 4));
            cp16(dst, g_wh + (size_t)(kc + row) * HH + h0 + u * 8);
        }
        cp_commit();
    };
    loadB(0);

    // ---- A slice pipeline: slice j=c&7 = h halves [j*64, j*64+64) = 128B/row.
    // 1024 16B-units per slice; thread covers 4 units (idx = tid + i*256,
    // row = idx>>3, u = idx&7). Held CONVERTED (hv[16] regs, not raw fp32).
    const float* asrc = enc + ((size_t)b * SS + s0) * HH;
    __half* edst = g_ench + ((size_t)b * SS + s0) * HH;
    uint32_t hv[16];

    auto ldgcvtA = [&](int c) {
        const int j = c & 7;
        #pragma unroll
        for (int i = 0; i < 4; i++) {
            int idx = tid + i * 256;
            int row = idx >> 3, u = idx & 7;
            const float4* p =
                (const float4*)(asrc + (size_t)row * HH + j * 64 + u * 8);
            float4 x = p[0], y = p[1];
            hv[4*i+0] = h2u(__floats2half2_rn(x.x, x.y));
            hv[4*i+1] = h2u(__floats2half2_rn(x.z, x.w));
            hv[4*i+2] = h2u(__floats2half2_rn(y.x, y.y));
            hv[4*i+3] = h2u(__floats2half2_rn(y.z, y.w));
        }
    };
    auto stsA = [&](int c) {
        const int j = c & 7;
        const uint32_t abuf = sbase + SM_A + (c & 1) * ABUF;
        #pragma unroll
        for (int i = 0; i < 4; i++) {
            int idx = tid + i * 256;
            int row = idx >> 3, u = idx & 7;
            uint32_t dst = abuf + row * 128 + ((u * 16) ^ ((row & 7) << 4));
            asm volatile("st.shared.v4.b32 [%0], {%1,%2,%3,%4};"
                         :: "r"(dst), "r"(hv[4*i]), "r"(hv[4*i+1]),
                            "r"(hv[4*i+2]), "r"(hv[4*i+3]));
            if (c < 8)
                *(uint4*)(edst + (size_t)row * HH + j * 64 + u * 8) =
                    make_uint4(hv[4*i], hv[4*i+1], hv[4*i+2], hv[4*i+3]);
        }
    };
    ldgcvtA(0);

    // ---- lane-constant ldmatrix addressing ----
    const int arow = warp_m * 64 + (lane & 7) + ((lane >> 3) & 1) * 8;   // +mi*16
    const int brow = warp_n * 32 + (lane & 7) + ((lane >> 3) & 1) * 8;   // +nip*16
    const int lcol16 = ((lane >> 4) & 1) * 16;    // +16B for k+8 halves
    const uint32_t xor_a = (arow & 7) << 4;
    const uint32_t xor_b = (brow & 7) << 4;

    float acc[4][4][4];   // [mi][ni][quad]
    #pragma unroll
    for (int mi = 0; mi < 4; mi++)
        #pragma unroll
        for (int ni = 0; ni < 4; ni++)
            #pragma unroll
            for (int q = 0; q < 4; q++) acc[mi][ni][q] = 0.f;

    #pragma unroll 1
    for (int c = 0; c < 32; c++) {
        stsA(c);                    // slice c (ldg+cvt'd during chunk c-1)
        if (c < 31) {
            loadB(c + 1);
            asm volatile("cp.async.wait_group 1;");
        } else {
            asm volatile("cp.async.wait_group 0;");
        }
        __syncthreads();

        const uint32_t abase = sbase + SM_A + (c & 1) * ABUF + arow * 128;
        const uint32_t bb = sbase + SM_B + (c & 1) * BBUF + brow * 128;

        #pragma unroll
        for (int kk = 0; kk < 4; kk++) {
            const uint32_t hoff = (uint32_t)(kk * 32 + lcol16);
            uint32_t a[4][4];
            #pragma unroll
            for (int mi = 0; mi < 4; mi++)
                ldsm4(a[mi], abase + mi * 2048 + (hoff ^ xor_a));
            #pragma unroll
            for (int nip = 0; nip < 2; nip++) {
                uint32_t r[4];
                ldsm4(r, bb + nip * 2048 + (hoff ^ xor_b));
                #pragma unroll
                for (int mi = 0; mi < 4; mi++) {
                    mma_f16(acc[mi][2 * nip], a[mi], r[0], r[2]);
                    mma_f16(acc[mi][2 * nip + 1], a[mi], r[1], r[3]);
                }
            }
        }

        if ((c & 7) == 7) {
            // epilogue for pass p: tanh(acc + c)*v, reduce 32 k per warp
            const int kbase = ((c >> 3) << 7) + warp_n * 32;
            float rs[8];
            #pragma unroll
            for (int i = 0; i < 8; i++) rs[i] = 0.f;
            #pragma unroll
            for (int ni = 0; ni < 4; ni++) {
                int kg = kbase + ni * 8 + tg * 2;
                float c0 = cs[kg], c1 = cs[kg + 1];
                float v0 = vs[kg], v1 = vs[kg + 1];
                #pragma unroll
                for (int mi = 0; mi < 4; mi++) {
                    rs[mi * 2 + 0] += tanha(acc[mi][ni][0] + c0) * v0
                                    + tanha(acc[mi][ni][1] + c1) * v1;
                    rs[mi * 2 + 1] += tanha(acc[mi][ni][2] + c0) * v0
                                    + tanha(acc[mi][ni][3] + c1) * v1;
                    acc[mi][ni][0] = 0.f; acc[mi][ni][1] = 0.f;
                    acc[mi][ni][2] = 0.f; acc[mi][ni][3] = 0.f;
                }
            }
            #pragma unroll
            for (int i = 0; i < 8; i++) {
                rs[i] += __shfl_xor_sync(0xffffffffu, rs[i], 1);
                rs[i] += __shfl_xor_sync(0xffffffffu, rs[i], 2);
            }
            if (tg == 0) {
                #pragma unroll
                for (int mi = 0; mi < 4; mi++) {
                    int row = warp_m * 64 + mi * 16 + g;
                    ssum[warp_n * 128 + row]     += rs[mi * 2 + 0];
                    ssum[warp_n * 128 + row + 8] += rs[mi * 2 + 1];
                }
            }
        }

        if (c < 31) ldgcvtA(c + 1);   // LDG stall at end of chunk; co-CTA covers
        __syncthreads();
    }

    if (tid < 128) {
        g_scores[b * SS + s0 + tid] =
            (ssum[tid] + ssum[128 + tid]) + (ssum[256 + tid] + ssum[384 + tid]);
    }
}

// ---------------------------------------------------------------------------
// Kernel C: softmax over s (2048) per batch; in-place on g_scores
// ---------------------------------------------------------------------------
__global__ void softmax_kernel() {
    __shared__ float red[256];
    int b = blockIdx.x, t = threadIdx.x;
    float v[8];
    float m = -1e30f;
    #pragma unroll
    for (int i = 0; i < 8; i++) {
        v[i] = g_scores[b * SS + i * 256 + t];
        m = fmaxf(m, v[i]);
    }
    red[t] = m;
    __syncthreads();
    for (int o = 128; o > 0; o >>= 1) {
        if (t < o) red[t] = fmaxf(red[t], red[t + o]);
        __syncthreads();
    }
    float mx = red[0];
    __syncthreads();
    float s = 0.f;
    #pragma unroll
    for (int i = 0; i < 8; i++) {
        v[i] = __expf(v[i] - mx);
        s += v[i];
    }
    red[t] = s;
    __syncthreads();
    for (int o = 128; o > 0; o >>= 1) {
        if (t < o) red[t] += red[t + o];
        __syncthreads();
    }
    float inv = 1.f / red[0];
    #pragma unroll
    for (int i = 0; i < 8; i++)
        g_scores[b * SS + i * 256 + t] = v[i] * inv;
}

// ---------------------------------------------------------------------------
// Kernel D: context partials over 128-s chunks, fp16 enc (from scores STG)
// grid(16, 64), block(128); thread t owns h = 4t..4t+3
// ---------------------------------------------------------------------------
__global__ void context_kernel() {
    __shared__ float ws[128];
    int b = blockIdx.y, sc = blockIdx.x;
    int t = threadIdx.x;
    ws[t] = g_scores[b * SS + sc * 128 + t];
    __syncthreads();
    const __half* ep = g_ench + ((size_t)b * SS + sc * 128) * HH + 4 * t;
    float ax = 0.f, ay = 0.f, az = 0.f, aw = 0.f;
    #pragma unroll 4
    for (int j = 0; j < 128; j++) {
        float w = ws[j];
        uint2 u = *(const uint2*)(ep + (size_t)j * HH);
        float2 f0 = __half22float2(*reinterpret_cast<const __half2*>(&u.x));
        float2 f1 = __half22float2(*reinterpret_cast<const __half2*>(&u.y));
        ax += w * f0.x; ay += w * f0.y; az += w * f1.x; aw += w * f1.y;
    }
    float4 r; r.x = ax; r.y = ay; r.z = az; r.w = aw;
    ((float4*)(g_part + ((size_t)(b * 16 + sc)) * HH))[t] = r;
}

// ---------------------------------------------------------------------------
// Kernel E: reduce 16 partials -> context
// ---------------------------------------------------------------------------
__global__ void reduce_ctx(float* __restrict__ out) {
    int b = blockIdx.x, h = threadIdx.x;
    float s = 0.f;
    #pragma unroll
    for (int i = 0; i < 16; i++) s += g_part[((size_t)(b * 16 + i)) * HH + h];
    out[b * HH + h] = s;
}

// ---------------------------------------------------------------------------
extern "C" void kernel_launch(void* const* d_in, const int* in_sizes, int n_in,
                              void* d_out, int out_size) {
    const float* enc    = (const float*)d_in[0];   // (64, 2048, 512)
    const float* fin    = (const float*)d_in[1];   // (64, 512)
    const float* attn_w = (const float*)d_in[2];   // (512, 1024)
    const float* attn_b = (const float*)d_in[3];   // (512,)
    const float* v_w    = (const float*)d_in[4];   // (1, 512)
    float* out = (float*)d_out;                    // (64, 512)

    cudaFuncSetAttribute(scores_fp16,
                         cudaFuncAttributeMaxDynamicSharedMemorySize, SMEM_BYTES);

    conv_w_kernel<<<KK, 256>>>(attn_w);
    cvec_kernel<<<BB, 256>>>(fin, attn_w, attn_b);
    scores_fp16<<<dim3(SS / 128, BB), 256, SMEM_BYTES>>>(enc, v_w);
    softmax_kernel<<<BB, 256>>>();
    context_kernel<<<dim3(16, BB), 128>>>();
    reduce_ctx<<<BB, 512>>>(out);
}

// round 16
// speedup vs baseline: 1.3984x; 1.0157x over previous
#include <cuda_runtime.h>
#include <cuda_fp16.h>
#include <cstdint>

// Problem constants
#define BB 64
#define SS 2048
#define HH 512
#define KK 512

// Scratch (static __device__ — no allocation)
__device__ float  g_c[BB * KK];            // e_fin + bias
__device__ float  g_scores[BB * SS];       // scores, then softmax weights
__device__ float  g_part[BB * 16 * HH];    // context partial sums
__device__ __half g_ench[(size_t)BB * SS * HH];   // enc in fp16 (written by scores)
__device__ __half g_wh[KK * HH];                  // w_enc in fp16

// ---------------------------------------------------------------------------
// helpers
// ---------------------------------------------------------------------------
__device__ __forceinline__ float tanha(float x) {
    float y;
    asm("tanh.approx.f32 %0, %1;" : "=f"(y) : "f"(x));
    return y;
}
__device__ __forceinline__ void cp16(uint32_t dst, const void* src) {
    asm volatile("cp.async.cg.shared.global [%0], [%1], 16;" :: "r"(dst), "l"(src));
}
__device__ __forceinline__ void cp_commit() {
    asm volatile("cp.async.commit_group;");
}
__device__ __forceinline__ void ldsm4(uint32_t (&r)[4], uint32_t addr) {
    asm volatile("ldmatrix.sync.aligned.m8n8.x4.shared.b16 {%0,%1,%2,%3}, [%4];"
                 : "=r"(r[0]), "=r"(r[1]), "=r"(r[2]), "=r"(r[3]) : "r"(addr));
}
__device__ __forceinline__ void mma_f16(float (&d)[4], const uint32_t (&a)[4],
                                        uint32_t b0, uint32_t b1) {
    asm volatile(
        "mma.sync.aligned.m16n8k16.row.col.f32.f16.f16.f32 "
        "{%0,%1,%2,%3},{%4,%5,%6,%7},{%8,%9},{%0,%1,%2,%3};"
        : "+f"(d[0]), "+f"(d[1]), "+f"(d[2]), "+f"(d[3])
        : "r"(a[0]), "r"(a[1]), "r"(a[2]), "r"(a[3]), "r"(b0), "r"(b1));
}
__device__ __forceinline__ uint32_t h2u(__half2 h) {
    return *reinterpret_cast<uint32_t*>(&h);
}

// ---------------------------------------------------------------------------
// conv_w: w_enc fp32 -> fp16
// ---------------------------------------------------------------------------
__global__ void conv_w_kernel(const float* __restrict__ attn_w) {
    int k = blockIdx.x, t = threadIdx.x;
    float2 v = *(const float2*)(attn_w + (size_t)k * (2 * HH) + 2 * t);
    ((__half2*)g_wh)[k * (HH / 2) + t] = __floats2half2_rn(v.x, v.y);
}

// ---------------------------------------------------------------------------
// Kernel A: c[b,k] = dot(fin[b,:], attn_w[k, 512:1024]) + attn_b[k]  (fp32)
// ---------------------------------------------------------------------------
__global__ void cvec_kernel(const float* __restrict__ fin,
                            const float* __restrict__ attn_w,
                            const float* __restrict__ attn_b) {
    __shared__ float fsm[HH];
    int b = blockIdx.x;
    int t = threadIdx.x;
    fsm[t] = fin[b * HH + t];
    fsm[t + 256] = fin[b * HH + t + 256];
    __syncthreads();

    int warp = t >> 5, lane = t & 31;
    for (int k = warp; k < KK; k += 8) {
        const float* wp = attn_w + (size_t)k * (2 * HH) + HH;
        float s = 0.f;
        #pragma unroll 4
        for (int h = lane; h < HH; h += 32) s += fsm[h] * wp[h];
        #pragma unroll
        for (int o = 16; o > 0; o >>= 1) s += __shfl_xor_sync(0xffffffffu, s, o);
        if (lane == 0) g_c[b * KK + k] = s + attn_b[k];
    }
}

// ---------------------------------------------------------------------------
// sep_kernel: no-op separator so scores_fp16 sits at launch index 3, which is
// the launch ncu's bounded capture profiles (empirical: R3/R4/R6/R10/R15).
// ---------------------------------------------------------------------------
__global__ void sep_kernel() {}

// ---------------------------------------------------------------------------
// Kernel B: fused scores = sum_k v[k]*tanh(enc @ w_enc^T + c), fp16 mma.
// grid(16, 64): 128-s tile (x), batch (y). 512 thr = 16 warps (2 warp_m x 8
// warp_n), warp tile 64m x 32k. Block n-tile 256, 2 kc passes.
// A (fp32 enc) loaded, converted and STS'd slice-by-slice, software-pipelined
// under the mma mainloop; fp16 copy STG'd to g_ench for the context kernel.
// B (w, fp16) double-buffered cp.async, 64-h chunks.  (R10 config — best.)
//
// SMEM (bytes): cs[512]f32 @0, vs[512]f32 @2048, ssum[8][128]f32 @4096,
//               A @8192 (128 rows x 1024B, XOR16 swizzle),
//               B @139264 (2 bufs x 256 rows x 128B, XOR16 swizzle)
// ---------------------------------------------------------------------------
#define SM_CS   0
#define SM_VS   2048
#define SM_SSUM 4096
#define SM_A    8192
#define SM_B    139264
#define BBUF    32768
#define SMEM_BYTES 204800

extern __shared__ uint32_t sdyn[];

__global__ __launch_bounds__(512, 1) void scores_fp16(
    const float* __restrict__ enc, const float* __restrict__ vw) {
    const int b = blockIdx.y;
    const int s0 = blockIdx.x * 128;
    const int tid = threadIdx.x;
    const int warp = tid >> 5, lane = tid & 31;
    const int g = lane >> 2, tg = lane & 3;
    const int warp_m = warp >> 3;      // 0..1  -> 64-row slices
    const int warp_n = warp & 7;       // 0..7  -> 32-k slices
    const uint32_t sbase = (uint32_t)__cvta_generic_to_shared(sdyn);

    float* cs = (float*)((char*)sdyn + SM_CS);
    float* vs = (float*)((char*)sdyn + SM_VS);
    float* ssum = (float*)((char*)sdyn + SM_SSUM);

    cs[tid] = g_c[b * KK + tid];
    vs[tid] = vw[tid];
    ssum[tid] = 0.f;
    ssum[tid + 512] = 0.f;

    // ---- B chunk loader: kc=(c>>3)*256, h0=(c&7)*64 halves ----
    auto loadB = [&](int c) {
        const uint32_t bb = sbase + SM_B + (c & 1) * BBUF;
        const int kc = (c >> 3) << 8;
        const int h0 = (c & 7) << 6;
        #pragma unroll
        for (int i = 0; i < 4; i++) {
            int idx = tid + i * 512;
            int row = idx >> 3, c16 = idx & 7;
            uint32_t dst = bb + row * 128 + ((c16 * 16) ^ ((row & 7) << 4));
            cp16(dst, g_wh + (size_t)(kc + row) * HH + h0 + c16 * 8);
        }
        cp_commit();
    };
    loadB(0);

    // ---- A slice pipeline: slice j covers h halves [j*64, j*64+64) ----
    // thread t owns 2 16B-units: rows ar0 (0..63) and ar1 (64..127).
    const float* asrc = enc + ((size_t)b * SS + s0) * HH;
    __half* edst = g_ench + ((size_t)b * SS + s0) * HH;
    const int ar0 = tid >> 3, au0 = (tid & 7);
    const int ar1 = ar0 + 64;
    float4 ax0, ay0, ax1, ay1;

    auto ldgA = [&](int j) {
        const float* p0 = asrc + (size_t)ar0 * HH + j * 64 + au0 * 8;
        const float* p1 = asrc + (size_t)ar1 * HH + j * 64 + au0 * 8;
        ax0 = ((const float4*)p0)[0];
        ay0 = ((const float4*)p0)[1];
        ax1 = ((const float4*)p1)[0];
        ay1 = ((const float4*)p1)[1];
    };
    auto stsA = [&](int j) {
        uint32_t w0 = h2u(__floats2half2_rn(ax0.x, ax0.y));
        uint32_t w1 = h2u(__floats2half2_rn(ax0.z, ax0.w));
        uint32_t w2 = h2u(__floats2half2_rn(ay0.x, ay0.y));
        uint32_t w3 = h2u(__floats2half2_rn(ay0.z, ay0.w));
        uint32_t col = (uint32_t)(j * 128 + au0 * 16);
        uint32_t d0 = sbase + SM_A + ar0 * 1024 + (col ^ ((ar0 & 7) << 4));
        asm volatile("st.shared.v4.b32 [%0], {%1,%2,%3,%4};"
                     :: "r"(d0), "r"(w0), "r"(w1), "r"(w2), "r"(w3));
        *(uint4*)(edst + (size_t)ar0 * HH + j * 64 + au0 * 8) =
            make_uint4(w0, w1, w2, w3);
        uint32_t u0 = h2u(__floats2half2_rn(ax1.x, ax1.y));
        uint32_t u1 = h2u(__floats2half2_rn(ax1.z, ax1.w));
        uint32_t u2 = h2u(__floats2half2_rn(ay1.x, ay1.y));
        uint32_t u3 = h2u(__floats2half2_rn(ay1.z, ay1.w));
        uint32_t d1 = sbase + SM_A + ar1 * 1024 + (col ^ ((ar1 & 7) << 4));
        asm volatile("st.shared.v4.b32 [%0], {%1,%2,%3,%4};"
                     :: "r"(d1), "r"(u0), "r"(u1), "r"(u2), "r"(u3));
        *(uint4*)(edst + (size_t)ar1 * HH + j * 64 + au0 * 8) =
            make_uint4(u0, u1, u2, u3);
    };
    ldgA(0);

    // ---- lane-constant ldmatrix addressing ----
    const int arow = warp_m * 64 + (lane & 7) + ((lane >> 3) & 1) * 8;   // +mi*16
    const int brow = warp_n * 32 + (lane & 7) + ((lane >> 3) & 1) * 8;   // +nip*16
    const int lcol16 = ((lane >> 4) & 1) * 16;    // +16B for k+8 matrices
    const uint32_t a_lane = sbase + SM_A + arow * 1024;
    const uint32_t xor_a = (arow & 7) << 4;
    const uint32_t xor_b = (brow & 7) << 4;

    float acc[4][4][4];
    #pragma unroll
    for (int mi = 0; mi < 4; mi++)
        #pragma unroll
        for (int ni = 0; ni < 4; ni++)
            #pragma unroll
            for (int q = 0; q < 4; q++) acc[mi][ni][q] = 0.f;

    #pragma unroll 1
    for (int c = 0; c < 16; c++) {
        if (c < 8) stsA(c);         // slice c -> smem (visible after barrier)
        if (c < 15) {
            loadB(c + 1);
            asm volatile("cp.async.wait_group 1;");
        } else {
            asm volatile("cp.async.wait_group 0;");
        }
        __syncthreads();
        if (c < 7) ldgA(c + 1);     // hidden under this chunk's mma

        const uint32_t bb = sbase + SM_B + (c & 1) * BBUF + brow * 128;
        const int hbase = (c & 7) * 128;   // byte offset of chunk within A row

        #pragma unroll
        for (int kk = 0; kk < 4; kk++) {
            const uint32_t hoff = (uint32_t)(hbase + kk * 32 + lcol16);
            uint32_t a[4][4];
            #pragma unroll
            for (int mi = 0; mi < 4; mi++)
                ldsm4(a[mi], a_lane + mi * 16384 + (hoff ^ xor_a));
            #pragma unroll
            for (int nip = 0; nip < 2; nip++) {
                uint32_t r[4];
                ldsm4(r, bb + nip * 2048 + (((uint32_t)(kk * 32 + lcol16)) ^ xor_b));
                #pragma unroll
                for (int mi = 0; mi < 4; mi++) {
                    mma_f16(acc[mi][2 * nip], a[mi], r[0], r[2]);
                    mma_f16(acc[mi][2 * nip + 1], a[mi], r[1], r[3]);
                }
            }
        }

        if ((c & 7) == 7) {
            // epilogue for this kc: tanh(acc + c)*v, reduce 32 k per warp
            const int kc = (c >> 3) << 8;
            float rs[8];
            #pragma unroll
            for (int i = 0; i < 8; i++) rs[i] = 0.f;
            #pragma unroll
            for (int ni = 0; ni < 4; ni++) {
                int kg = kc + warp_n * 32 + ni * 8 + tg * 2;
                float c0 = cs[kg], c1 = cs[kg + 1];
                float v0 = vs[kg], v1 = vs[kg + 1];
                #pragma unroll
                for (int mi = 0; mi < 4; mi++) {
                    rs[mi * 2 + 0] += tanha(acc[mi][ni][0] + c0) * v0
                                    + tanha(acc[mi][ni][1] + c1) * v1;
                    rs[mi * 2 + 1] += tanha(acc[mi][ni][2] + c0) * v0
                                    + tanha(acc[mi][ni][3] + c1) * v1;
                    acc[mi][ni][0] = 0.f; acc[mi][ni][1] = 0.f;
                    acc[mi][ni][2] = 0.f; acc[mi][ni][3] = 0.f;
                }
            }
            #pragma unroll
            for (int i = 0; i < 8; i++) {
                rs[i] += __shfl_xor_sync(0xffffffffu, rs[i], 1);
                rs[i] += __shfl_xor_sync(0xffffffffu, rs[i], 2);
            }
            if (tg == 0) {
                #pragma unroll
                for (int mi = 0; mi < 4; mi++) {
                    int row = warp_m * 64 + mi * 16 + g;
                    ssum[warp_n * 128 + row]     += rs[mi * 2 + 0];
                    ssum[warp_n * 128 + row + 8] += rs[mi * 2 + 1];
                }
            }
        }
        __syncthreads();
    }

    if (tid < 128) {
        float s = 0.f;
        #pragma unroll
        for (int wn = 0; wn < 8; wn++) s += ssum[wn * 128 + tid];
        g_scores[b * SS + s0 + tid] = s;
    }
}

// ---------------------------------------------------------------------------
// Kernel C: softmax over s (2048) per batch; in-place on g_scores
// ---------------------------------------------------------------------------
__global__ void softmax_kernel() {
    __shared__ float red[256];
    int b = blockIdx.x, t = threadIdx.x;
    float v[8];
    float m = -1e30f;
    #pragma unroll
    for (int i = 0; i < 8; i++) {
        v[i] = g_scores[b * SS + i * 256 + t];
        m = fmaxf(m, v[i]);
    }
    red[t] = m;
    __syncthreads();
    for (int o = 128; o > 0; o >>= 1) {
        if (t < o) red[t] = fmaxf(red[t], red[t + o]);
        __syncthreads();
    }
    float mx = red[0];
    __syncthreads();
    float s = 0.f;
    #pragma unroll
    for (int i = 0; i < 8; i++) {
        v[i] = __expf(v[i] - mx);
        s += v[i];
    }
    red[t] = s;
    __syncthreads();
    for (int o = 128; o > 0; o >>= 1) {
        if (t < o) red[t] += red[t + o];
        __syncthreads();
    }
    float inv = 1.f / red[0];
    #pragma unroll
    for (int i = 0; i < 8; i++)
        g_scores[b * SS + i * 256 + t] = v[i] * inv;
}

// ---------------------------------------------------------------------------
// Kernel D: context partials over 128-s chunks, fp16 enc, uint4 loads
// (16 B/LDG -> half the LDG count of the uint2 version; LDG-issue bound).
// grid(16, 64), block(128): thread t -> h group hg=t&63 (8 halves),
// row parity rg=t>>6; 64 iters x 2 rows. rg-pair reduced via smem.
// ---------------------------------------------------------------------------
__global__ void context_kernel() {
    __shared__ float ws[128];
    __shared__ float red[64 * 8];
    int b = blockIdx.y, sc = blockIdx.x;
    int t = threadIdx.x;
    ws[t] = g_scores[b * SS + sc * 128 + t];
    __syncthreads();
    const int hg = t & 63, rg = t >> 6;
    const __half* ep =
        g_ench + ((size_t)b * SS + sc * 128 + rg) * HH + hg * 8;
    float a0 = 0.f, a1 = 0.f, a2 = 0.f, a3 = 0.f;
    float a4 = 0.f, a5 = 0.f, a6 = 0.f, a7 = 0.f;
    #pragma unroll 4
    for (int j = 0; j < 64; j++) {
        float w = ws[j * 2 + rg];
        uint4 u = *(const uint4*)(ep + (size_t)j * 2 * HH);
        float2 f0 = __half22float2(*reinterpret_cast<const __half2*>(&u.x));
        float2 f1 = __half22float2(*reinterpret_cast<const __half2*>(&u.y));
        float2 f2 = __half22float2(*reinterpret_cast<const __half2*>(&u.z));
        float2 f3 = __half22float2(*reinterpret_cast<const __half2*>(&u.w));
        a0 += w * f0.x; a1 += w * f0.y; a2 += w * f1.x; a3 += w * f1.y;
        a4 += w * f2.x; a5 += w * f2.y; a6 += w * f3.x; a7 += w * f3.y;
    }
    if (rg == 1) {
        float* r = red + hg * 8;
        r[0] = a0; r[1] = a1; r[2] = a2; r[3] = a3;
        r[4] = a4; r[5] = a5; r[6] = a6; r[7] = a7;
    }
    __syncthreads();
    if (rg == 0) {
        const float* r = red + hg * 8;
        float4 o0, o1;
        o0.x = a0 + r[0]; o0.y = a1 + r[1]; o0.z = a2 + r[2]; o0.w = a3 + r[3];
        o1.x = a4 + r[4]; o1.y = a5 + r[5]; o1.z = a6 + r[6]; o1.w = a7 + r[7];
        float4* dst = (float4*)(g_part + ((size_t)(b * 16 + sc)) * HH + hg * 8);
        dst[0] = o0;
        dst[1] = o1;
    }
}

// ---------------------------------------------------------------------------
// Kernel E: reduce 16 partials -> context
// ---------------------------------------------------------------------------
__global__ void reduce_ctx(float* __restrict__ out) {
    int b = blockIdx.x, h = threadIdx.x;
    float s = 0.f;
    #pragma unroll
    for (int i = 0; i < 16; i++) s += g_part[((size_t)(b * 16 + i)) * HH + h];
    out[b * HH + h] = s;
}

// ---------------------------------------------------------------------------
extern "C" void kernel_launch(void* const* d_in, const int* in_sizes, int n_in,
                              void* d_out, int out_size) {
    const float* enc    = (const float*)d_in[0];   // (64, 2048, 512)
    const float* fin    = (const float*)d_in[1];   // (64, 512)
    const float* attn_w = (const float*)d_in[2];   // (512, 1024)
    const float* attn_b = (const float*)d_in[3];   // (512,)
    const float* v_w    = (const float*)d_in[4];   // (1, 512)
    float* out = (float*)d_out;                    // (64, 512)

    cudaFuncSetAttribute(scores_fp16,
                         cudaFuncAttributeMaxDynamicSharedMemorySize, SMEM_BYTES);

    conv_w_kernel<<<KK, 256>>>(attn_w);            // launch 0
    cvec_kernel<<<BB, 256>>>(fin, attn_w, attn_b); // launch 1
    sep_kernel<<<1, 32>>>();                       // launch 2 (aligns ncu)
    scores_fp16<<<dim3(SS / 128, BB), 512, SMEM_BYTES>>>(enc, v_w); // launch 3
    softmax_kernel<<<BB, 256>>>();                 // launch 4
    context_kernel<<<dim3(16, BB), 128>>>();       // launch 5
    reduce_ctx<<<BB, 512>>>(out);                  // launch 6
}